// round 10
// baseline (speedup 1.0000x reference)
#include <cuda_runtime.h>
#include <cuda_fp16.h>
#include <math.h>

// Problem constants
#define B_  16
#define N_  2048
#define E_  1024
#define G_  2
#define V_  320
#define D_  512
#define GV_ 640
#define M_  (B_ * N_)
#define ROWS_ (M_ * G_)

#define BK   32
#define NIT  (E_ / BK)       // 32
#define APITCH 40            // fp16 elems per smem row (80B, ldsm conflict-free)
#define THRESH 0.05f

// Dynamic smem: 3 stages x (A 256x40 + B 128x40) fp16
#define STG_BYTES  30720
#define SMEM_TOTAL 92160

// Device scratch (sanctioned: __device__ globals)
__device__ __half g_xh[(size_t)M_ * E_];   // x fp16
__device__ __half g_wh[(size_t)GV_ * E_];  // W^T fp16 [n][k]
__device__ __half g_hh[(size_t)M_ * GV_];  // logits fp16 (42 MB)
__device__ int    g_counts[B_ * G_ * V_];

// ---------------------------------------------------------------------------
// PTX helpers
// ---------------------------------------------------------------------------
__device__ __forceinline__ unsigned smem_u32(const void* p) {
    unsigned a;
    asm("{ .reg .u64 t; cvta.to.shared.u64 t, %1; cvt.u32.u64 %0, t; }"
        : "=r"(a) : "l"(p));
    return a;
}
__device__ __forceinline__ void cp_async16(unsigned dst, const void* src) {
    asm volatile("cp.async.cg.shared.global [%0], [%1], 16;" :: "r"(dst), "l"(src));
}
__device__ __forceinline__ void cp_commit() {
    asm volatile("cp.async.commit_group;" ::: "memory");
}
__device__ __forceinline__ void cp_wait0() { asm volatile("cp.async.wait_group 0;" ::: "memory"); }
__device__ __forceinline__ void cp_wait1() { asm volatile("cp.async.wait_group 1;" ::: "memory"); }

__device__ __forceinline__ void ldsm4(unsigned* r, unsigned addr) {
    asm volatile("ldmatrix.sync.aligned.m8n8.x4.shared.b16 {%0,%1,%2,%3}, [%4];"
                 : "=r"(r[0]), "=r"(r[1]), "=r"(r[2]), "=r"(r[3]) : "r"(addr));
}
// f16 x f16 -> f16 accumulate (2x rate vs f32 accum on this pipe)
__device__ __forceinline__ void mma16816h(unsigned* c, const unsigned* a,
                                          unsigned b0, unsigned b1) {
    asm volatile(
        "mma.sync.aligned.m16n8k16.row.col.f16.f16.f16.f16 "
        "{%0,%1}, {%2,%3,%4,%5}, {%6,%7}, {%0,%1};"
        : "+r"(c[0]), "+r"(c[1])
        : "r"(a[0]), "r"(a[1]), "r"(a[2]), "r"(a[3]), "r"(b0), "r"(b1));
}

// Issue one k-tile: 2 A rows + 1 B row chunk per thread (3 x 16B),
// lanes 4t..4t+3 contiguous 64B -> full 32B-sector utilization.
__device__ __forceinline__ void issue_tile(unsigned dA, unsigned dB,
                                           const __half* ag, const __half* bg) {
    cp_async16(dA,         ag);
    cp_async16(dA + 10240, ag + (size_t)128 * E_);   // rows +128
    cp_async16(dB,         bg);
    cp_commit();
}

// ---------------------------------------------------------------------------
// Kernel 0: zero histograms
// ---------------------------------------------------------------------------
__global__ void zero_counts_kernel() {
    int i = blockIdx.x * blockDim.x + threadIdx.x;
    if (i < B_ * G_ * V_) g_counts[i] = 0;
}

// ---------------------------------------------------------------------------
// Kernel 1a: convert x -> fp16
// ---------------------------------------------------------------------------
__global__ __launch_bounds__(256)
void convert_x_kernel(const float* __restrict__ x) {
    int i = blockIdx.x * blockDim.x + threadIdx.x;
    const int n4 = M_ * E_ / 4;
    if (i >= n4) return;
    float4 v = ((const float4*)x)[i];
    union { __half h[4]; uint2 u; } pk;
    pk.h[0] = __float2half_rn(v.x);
    pk.h[1] = __float2half_rn(v.y);
    pk.h[2] = __float2half_rn(v.z);
    pk.h[3] = __float2half_rn(v.w);
    ((uint2*)g_xh)[i] = pk.u;
}

// ---------------------------------------------------------------------------
// Kernel 1b: transpose+convert W -> W^T fp16
// ---------------------------------------------------------------------------
__global__ __launch_bounds__(256)
void convert_w_kernel(const float* __restrict__ W) {
    int i = blockIdx.x * blockDim.x + threadIdx.x;
    if (i >= GV_ * E_) return;
    int n = i >> 10;
    int k = i & 1023;
    g_wh[i] = __float2half_rn(W[(size_t)k * GV_ + n]);
}

// ---------------------------------------------------------------------------
// Kernel 2: fp16 tensor-core GEMM h = x @ W (f16 accumulate).
// BM=256, BN=128, BK=32; 512 thr = 16 warps (4 x 4), warp tile 64x32.
// 3-stage cp.async pipeline (proven R6 structure).
// ---------------------------------------------------------------------------
__global__ __launch_bounds__(512, 1)
void mma_gemm_kernel() {
    extern __shared__ __align__(16) __half smem[];

    const int tid  = threadIdx.x;
    const int lane = tid & 31;
    const int wid  = tid >> 5;           // 0..15
    const int bm = blockIdx.y * 256;
    const int bn = blockIdx.x * 128;
    const int wm = (wid & 3) * 64;
    const int wn = (wid >> 2) * 32;

    const int arow  = tid >> 2;          // 0..127
    const int acoff = (tid & 3) * 8;     // 0,8,16,24

    const __half* ag = g_xh + (size_t)(bm + arow) * E_ + acoff;
    const __half* bg = g_wh + (size_t)(bn + arow) * E_ + acoff;

    const unsigned sBase = smem_u32(&smem[0]);
    const unsigned dA = sBase + (unsigned)(arow * APITCH + acoff) * 2u;
    const unsigned dB = sBase + 20480u + (unsigned)(arow * APITCH + acoff) * 2u;

    // f16 accumulators: 4 mi x 4 n8-tiles x 2 packed regs
    unsigned acc[4][4][2];
    for (int i = 0; i < 4; i++)
        for (int j = 0; j < 4; j++) {
            acc[i][j][0] = 0u;
            acc[i][j][1] = 0u;
        }

    issue_tile(dA, dB, ag, bg);
    issue_tile(dA + STG_BYTES, dB + STG_BYTES, ag + BK, bg + BK);

    const int arow_f = wm + (lane & 15);
    const int acol_f = (lane >> 4) * 8;
    const unsigned aBase = sBase + (unsigned)(arow_f * APITCH + acol_f) * 2u;
    const int brow_f = wn + (lane & 7) + ((lane >> 4) << 3);
    const int bcol_f = ((lane >> 3) & 1) * 8;
    const unsigned bBase = sBase + 20480u + (unsigned)(brow_f * APITCH + bcol_f) * 2u;

    for (int it = 0; it < NIT; ++it) {
        const int s = it % 3;
        if (it == NIT - 1) cp_wait0(); else cp_wait1();
        __syncthreads();

        if (it + 2 < NIT) {
            const int s2 = (it + 2) % 3;
            issue_tile(dA + (unsigned)(s2 * STG_BYTES),
                       dB + (unsigned)(s2 * STG_BYTES),
                       ag + (it + 2) * BK, bg + (it + 2) * BK);
        }

        const unsigned so = (unsigned)(s * STG_BYTES);
#pragma unroll
        for (int kk = 0; kk < 2; ++kk) {
            unsigned af[4][4];
            unsigned bf[2][4];
#pragma unroll
            for (int mi = 0; mi < 4; ++mi)
                ldsm4(af[mi], aBase + so + (unsigned)(mi * 16 * APITCH + kk * 16) * 2u);
#pragma unroll
            for (int p = 0; p < 2; ++p)
                ldsm4(bf[p], bBase + so + (unsigned)(p * 16 * APITCH + kk * 16) * 2u);
#pragma unroll
            for (int mi = 0; mi < 4; ++mi) {
#pragma unroll
                for (int p = 0; p < 2; ++p) {
                    mma16816h(acc[mi][2 * p],     af[mi], bf[p][0], bf[p][1]);
                    mma16816h(acc[mi][2 * p + 1], af[mi], bf[p][2], bf[p][3]);
                }
            }
        }
    }

    // Epilogue: f16 d-fragments -> direct packed stores to g_hh.
    // reg0 = rows cg, cols (tg*2, tg*2+1); reg1 = rows cg+8, same cols.
    const int cg = lane >> 2;
    const int tg = lane & 3;
#pragma unroll
    for (int mi = 0; mi < 4; ++mi) {
        const int row = bm + wm + mi * 16 + cg;
        unsigned* o0 = (unsigned*)(g_hh + (size_t)row * GV_ + bn + wn + tg * 2);
        unsigned* o1 = (unsigned*)(g_hh + (size_t)(row + 8) * GV_ + bn + wn + tg * 2);
#pragma unroll
        for (int ni = 0; ni < 4; ++ni) {
            o0[ni * 4] = acc[mi][ni][0];
            o1[ni * 4] = acc[mi][ni][1];
        }
    }
}

// ---------------------------------------------------------------------------
// Kernel 3: argmax + exact rescue + histogram + gather. One warp per row.
// h is fp16; THRESH covers f16-chain accumulation noise (~25 sigma).
// ---------------------------------------------------------------------------
__global__ __launch_bounds__(256)
void argmax_gather_kernel(const float* __restrict__ x,
                          const float* __restrict__ u,
                          const float* __restrict__ W,
                          const float* __restrict__ bias,
                          const float* __restrict__ codebook,
                          float* __restrict__ out) {
    const int warp = (blockIdx.x * blockDim.x + threadIdx.x) >> 5;
    const int lane = threadIdx.x & 31;
    if (warp >= ROWS_) return;

    const int r    = warp;
    const int gidx = r & 1;
    const __half* hrow = g_hh + (size_t)r * V_;
    const float* urow = u + (size_t)r * V_;
    const float* brow = bias + gidx * V_;

    const float kA = 1.0f - 2.0f * 1e-7f;
    const float kB = 1e-7f;

    float vals[10];
    float best = -3.4e38f;
    int   bi   = 0;
#pragma unroll
    for (int i = 0; i < 10; i++) {
        const int v = i * 32 + lane;
        float uu = fmaf(urow[v], kA, kB);
        float gn = -logf(-logf(uu));
        float val = __half2float(hrow[v]) + brow[v] + gn;
        vals[i] = val;
        if (val > best) { best = val; bi = v; }
    }
#pragma unroll
    for (int off = 16; off; off >>= 1) {
        float ov = __shfl_down_sync(0xffffffffu, best, off);
        int   oi = __shfl_down_sync(0xffffffffu, bi, off);
        if (ov > best || (ov == best && oi < bi)) { best = ov; bi = oi; }
    }
    best = __shfl_sync(0xffffffffu, best, 0);
    bi   = __shfl_sync(0xffffffffu, bi, 0);

    float second = -3.4e38f;
#pragma unroll
    for (int i = 0; i < 10; i++) {
        const int v = i * 32 + lane;
        if (v != bi) second = fmaxf(second, vals[i]);
    }
#pragma unroll
    for (int off = 16; off; off >>= 1)
        second = fmaxf(second, __shfl_xor_sync(0xffffffffu, second, off));

    if (best - second < THRESH) {
        const float* xrow = x + (size_t)(r >> 1) * E_;
        float ex_best = -3.4e38f;
        int   ex_bi   = V_;
        const float cut = best - THRESH;
        for (int i = 0; i < 10; i++) {
            unsigned bal = __ballot_sync(0xffffffffu, vals[i] >= cut);
            while (bal) {
                const int j = __ffs(bal) - 1;
                bal &= bal - 1;
                const int vc = i * 32 + j;
                const int c  = gidx * V_ + vc;
                float s = 0.0f;
                for (int k = lane; k < E_; k += 32)
                    s = fmaf(xrow[k], W[(size_t)k * GV_ + c], s);
#pragma unroll
                for (int off = 16; off; off >>= 1)
                    s += __shfl_xor_sync(0xffffffffu, s, off);
                float uu = fmaf(urow[vc], kA, kB);
                float ex = s + brow[vc] + (-logf(-logf(uu)));
                if (ex > ex_best || (ex == ex_best && vc < ex_bi)) {
                    ex_best = ex;
                    ex_bi   = vc;
                }
            }
        }
        bi = ex_bi;
    }

    if (lane == 0) {
        int b = r >> 12;
        atomicAdd(&g_counts[(b * G_ + gidx) * V_ + bi], 1);
    }

    const float4* cb = (const float4*)(codebook + ((size_t)(gidx * V_ + bi)) * D_);
    float4*       op = (float4*)(out + (size_t)r * D_);
#pragma unroll
    for (int i = 0; i < 4; i++)
        op[i * 32 + lane] = cb[i * 32 + lane];
}

// ---------------------------------------------------------------------------
// Kernel 4: entropy from histograms
// ---------------------------------------------------------------------------
__global__ void entropy_kernel(float* __restrict__ out, int out_size) {
    const int w    = threadIdx.x >> 5;
    const int lane = threadIdx.x & 31;
    const int* c = g_counts + w * V_;

    float cv[10];
    float m = -3.4e38f;
#pragma unroll
    for (int i = 0; i < 10; i++) {
        cv[i] = (float)c[lane + i * 32];
        m = fmaxf(m, cv[i]);
    }
#pragma unroll
    for (int off = 16; off; off >>= 1)
        m = fmaxf(m, __shfl_xor_sync(0xffffffffu, m, off));

    float s = 0.0f;
#pragma unroll
    for (int i = 0; i < 10; i++)
        s += expf(cv[i] - m);
#pragma unroll
    for (int off = 16; off; off >>= 1)
        s += __shfl_xor_sync(0xffffffffu, s, off);

    float ent = 0.0f;
#pragma unroll
    for (int i = 0; i < 10; i++) {
        float p = expf(cv[i] - m) / s;
        ent += p * logf(p + 1e-8f);
    }
#pragma unroll
    for (int off = 16; off; off >>= 1)
        ent += __shfl_xor_sync(0xffffffffu, ent, off);

    __shared__ float part[32];
    if (lane == 0) part[w] = ent;
    __syncthreads();
    if (threadIdx.x == 0) {
        float t = 0.0f;
#pragma unroll
        for (int i = 0; i < 32; i++)
            t += part[i];
        out[out_size - 1] = -t / (float)(G_ * V_);
    }
}

// ---------------------------------------------------------------------------
extern "C" void kernel_launch(void* const* d_in, const int* in_sizes, int n_in,
                              void* d_out, int out_size) {
    const float* x        = (const float*)d_in[0];
    const float* u        = (const float*)d_in[1];
    const float* W        = (const float*)d_in[2];
    const float* bias     = (const float*)d_in[3];
    const float* codebook = (const float*)d_in[4];
    float* out = (float*)d_out;
    (void)in_sizes; (void)n_in;

    cudaFuncSetAttribute(mma_gemm_kernel,
                         cudaFuncAttributeMaxDynamicSharedMemorySize, SMEM_TOTAL);

    zero_counts_kernel<<<(B_ * G_ * V_ + 255) / 256, 256>>>();

    convert_x_kernel<<<(M_ * E_ / 4 + 255) / 256, 256>>>(x);
    convert_w_kernel<<<(GV_ * E_ + 255) / 256, 256>>>(W);

    dim3 gg(GV_ / 128, M_ / 256);   // (5, 128)
    mma_gemm_kernel<<<gg, 512, SMEM_TOTAL>>>();

    argmax_gather_kernel<<<(ROWS_ * 32 + 255) / 256, 256>>>(x, u, W, bias, codebook, out);

    entropy_kernel<<<1, 1024>>>(out, out_size);
}

// round 12
// speedup vs baseline: 1.0584x; 1.0584x over previous
#include <cuda_runtime.h>
#include <cuda_bf16.h>
#include <math.h>

// Problem constants
#define B_  16
#define N_  2048
#define E_  1024
#define G_  2
#define V_  320
#define D_  512
#define GV_ 640
#define M_  (B_ * N_)
#define ROWS_ (M_ * G_)

#define THRESH 0.05f

// Fused GEMM tiling: BM=64, BN=640 (full width), BK=32, 2-stage cp.async
#define BK    32
#define NIT   (E_ / BK)          // 32
#define A_ST  5120               /* 64 rows * 80 B (pitch 40 bf16) */
#define STG   56320              /* A + B per stage */
#define SMEM_DYN 112640          /* 2 stages (110 KB) */
#define NSLOTS 2816              /* (64+640)*4 cp.async 16B slots per stage */
#define HPITCH 648               /* h staging pitch in bf16 elems */

// Device scratch (sanctioned: __device__ globals)
__device__ __nv_bfloat16 g_xb[(size_t)M_ * E_];   // x bf16
__device__ __nv_bfloat16 g_wt[(size_t)GV_ * E_];  // W^T bf16 [n][k]
__device__ int           g_counts[B_ * G_ * V_];

// ---------------------------------------------------------------------------
// PTX helpers
// ---------------------------------------------------------------------------
__device__ __forceinline__ unsigned smem_u32(const void* p) {
    unsigned a;
    asm("{ .reg .u64 t; cvta.to.shared.u64 t, %1; cvt.u32.u64 %0, t; }"
        : "=r"(a) : "l"(p));
    return a;
}
__device__ __forceinline__ void cp_async16(unsigned dst, const void* src) {
    asm volatile("cp.async.cg.shared.global [%0], [%1], 16;" :: "r"(dst), "l"(src));
}
__device__ __forceinline__ void cp_commit() {
    asm volatile("cp.async.commit_group;" ::: "memory");
}
__device__ __forceinline__ void cp_wait0() { asm volatile("cp.async.wait_group 0;" ::: "memory"); }
__device__ __forceinline__ void cp_wait1() { asm volatile("cp.async.wait_group 1;" ::: "memory"); }

__device__ __forceinline__ void ldsm4(unsigned* r, unsigned addr) {
    asm volatile("ldmatrix.sync.aligned.m8n8.x4.shared.b16 {%0,%1,%2,%3}, [%4];"
                 : "=r"(r[0]), "=r"(r[1]), "=r"(r[2]), "=r"(r[3]) : "r"(addr));
}
__device__ __forceinline__ void mma16816(float* c, const unsigned* a,
                                         unsigned b0, unsigned b1) {
    asm volatile(
        "mma.sync.aligned.m16n8k16.row.col.f32.bf16.bf16.f32 "
        "{%0,%1,%2,%3}, {%4,%5,%6,%7}, {%8,%9}, {%0,%1,%2,%3};"
        : "+f"(c[0]), "+f"(c[1]), "+f"(c[2]), "+f"(c[3])
        : "r"(a[0]), "r"(a[1]), "r"(a[2]), "r"(a[3]), "r"(b0), "r"(b1));
}

// ---------------------------------------------------------------------------
// Kernel 0: zero histograms
// ---------------------------------------------------------------------------
__global__ void zero_counts_kernel() {
    int i = blockIdx.x * blockDim.x + threadIdx.x;
    if (i < B_ * G_ * V_) g_counts[i] = 0;
}

// ---------------------------------------------------------------------------
// Kernel 1a: convert x -> bf16
// ---------------------------------------------------------------------------
__global__ __launch_bounds__(256)
void convert_x_kernel(const float* __restrict__ x) {
    int i = blockIdx.x * blockDim.x + threadIdx.x;
    const int n4 = M_ * E_ / 4;
    if (i >= n4) return;
    float4 v = ((const float4*)x)[i];
    union { __nv_bfloat16 h[4]; uint2 u; } pk;
    pk.h[0] = __float2bfloat16(v.x);
    pk.h[1] = __float2bfloat16(v.y);
    pk.h[2] = __float2bfloat16(v.z);
    pk.h[3] = __float2bfloat16(v.w);
    ((uint2*)g_xb)[i] = pk.u;
}

// ---------------------------------------------------------------------------
// Kernel 1b: transpose+convert W -> W^T bf16
// ---------------------------------------------------------------------------
__global__ __launch_bounds__(256)
void convert_w_kernel(const float* __restrict__ W) {
    int i = blockIdx.x * blockDim.x + threadIdx.x;
    if (i >= GV_ * E_) return;
    int n = i >> 10;
    int k = i & 1023;
    g_wt[i] = __float2bfloat16(W[(size_t)k * GV_ + n]);
}

// ---------------------------------------------------------------------------
// Kernel 2 (FUSED): bf16 mma.sync GEMM h[64][640] per block + in-block
// gumbel argmax + exact fp32 rescue + histogram + codebook gather.
// 512 thr = 16 warps: wm = (wid&1)*32, wn = (wid>>1)*80 (warp tile 32x80).
// 2-stage pipeline, R5-proven ordering: wait/sync/compute/sync/issue.
// ---------------------------------------------------------------------------
__device__ __forceinline__ void issue_stage(unsigned sBase, int s, int it,
                                            int bm, int tid) {
    const unsigned stBase = sBase + (unsigned)(s * STG);
    const int k0 = it * BK;
    for (int slot = tid; slot < NSLOTS; slot += 512) {
        if (slot < 256) {
            const int row = slot >> 2;
            const int sec = slot & 3;
            cp_async16(stBase + (unsigned)(row * 80 + sec * 16),
                       g_xb + (size_t)(bm + row) * E_ + k0 + sec * 8);
        } else {
            const int t   = slot - 256;
            const int row = t >> 2;
            const int sec = t & 3;
            cp_async16(stBase + (unsigned)(A_ST + row * 80 + sec * 16),
                       g_wt + (size_t)row * E_ + k0 + sec * 8);
        }
    }
    cp_commit();
}

__global__ __launch_bounds__(512, 1)
void fused_gemm_argmax_kernel(const float* __restrict__ x,
                              const float* __restrict__ u,
                              const float* __restrict__ W,
                              const float* __restrict__ bias,
                              const float* __restrict__ codebook,
                              float* __restrict__ out) {
    extern __shared__ __align__(16) unsigned char dsm[];

    const int tid  = threadIdx.x;
    const int lane = tid & 31;
    const int wid  = tid >> 5;           // 0..15
    const int bm   = blockIdx.x * 64;
    const int wm   = (wid & 1) * 32;
    const int wn   = (wid >> 1) * 80;

    const unsigned sBase = smem_u32(dsm);

    float acc[2][10][4];
    for (int i = 0; i < 2; i++)
        for (int j = 0; j < 10; j++)
            for (int k = 0; k < 4; k++)
                acc[i][j][k] = 0.0f;

    // Prologue: 2 stages in flight
    issue_stage(sBase, 0, 0, bm, tid);
    issue_stage(sBase, 1, 1, bm, tid);

    // ldsm lane addressing (pitch 40 elems = 80 B)
    const int arow_f = wm + (lane & 15);
    const int acol_f = (lane >> 4) * 8;
    const unsigned aOff = (unsigned)(arow_f * 40 + acol_f) * 2u;
    const int brow_f = wn + (lane & 7) + ((lane >> 4) << 3);
    const int bcol_f = ((lane >> 3) & 1) * 8;
    const unsigned bOff = (unsigned)A_ST + (unsigned)(brow_f * 40 + bcol_f) * 2u;

    for (int it = 0; it < NIT; ++it) {
        const int s = it & 1;
        if (it == NIT - 1) cp_wait0(); else cp_wait1();
        __syncthreads();

        const unsigned so = sBase + (unsigned)(s * STG);
#pragma unroll
        for (int kk = 0; kk < 2; ++kk) {
            unsigned af[2][4];
#pragma unroll
            for (int mi = 0; mi < 2; ++mi)
                ldsm4(af[mi], so + aOff + (unsigned)(mi * 1280 + kk * 32));
#pragma unroll
            for (int p = 0; p < 5; ++p) {
                unsigned bf[4];
                ldsm4(bf, so + bOff + (unsigned)(p * 1280 + kk * 32));
#pragma unroll
                for (int mi = 0; mi < 2; ++mi) {
                    mma16816(acc[mi][2 * p],     af[mi], bf[0], bf[1]);
                    mma16816(acc[mi][2 * p + 1], af[mi], bf[2], bf[3]);
                }
            }
        }
        __syncthreads();

        if (it + 2 < NIT)
            issue_stage(sBase, s, it + 2, bm, tid);
    }

    // ---- Stage h[64][640] to smem as bf16 (reuse pipeline smem) ----
    __nv_bfloat16* hsm = (__nv_bfloat16*)dsm;
    const int cg = lane >> 2;
    const int tg = lane & 3;
#pragma unroll
    for (int mi = 0; mi < 2; ++mi) {
        const int r0 = wm + mi * 16 + cg;
#pragma unroll
        for (int ni = 0; ni < 10; ++ni) {
            const int col = wn + ni * 8 + tg * 2;
            float2 v0; v0.x = acc[mi][ni][0]; v0.y = acc[mi][ni][1];
            float2 v1; v1.x = acc[mi][ni][2]; v1.y = acc[mi][ni][3];
            *(__nv_bfloat162*)(hsm + (size_t)r0 * HPITCH + col)       = __float22bfloat162_rn(v0);
            *(__nv_bfloat162*)(hsm + (size_t)(r0 + 8) * HPITCH + col) = __float22bfloat162_rn(v1);
        }
    }
    __syncthreads();

    // ---- Argmax + rescue + histogram + gather: 128 (row,group) tasks ----
    const float kA = 1.0f - 2.0f * 1e-7f;
    const float kB = 1e-7f;

    for (int task = wid; task < 128; task += 16) {
        const int ri   = task >> 1;          // local row 0..63
        const int g    = task & 1;
        const int grow = bm + ri;            // global (b,n) row
        const __nv_bfloat16* hrow = hsm + (size_t)ri * HPITCH + g * V_;
        const float* urow = u + ((size_t)grow * 2 + g) * V_;
        const float* brow = bias + g * V_;

        float vals[10];
        float best = -3.4e38f;
        int   bi   = 0;
#pragma unroll
        for (int i = 0; i < 10; i++) {
            const int v = i * 32 + lane;
            float uu = fmaf(urow[v], kA, kB);
            float gn = -logf(-logf(uu));
            float val = __bfloat162float(hrow[v]) + brow[v] + gn;
            vals[i] = val;
            if (val > best) { best = val; bi = v; }
        }
#pragma unroll
        for (int off = 16; off; off >>= 1) {
            float ov = __shfl_down_sync(0xffffffffu, best, off);
            int   oi = __shfl_down_sync(0xffffffffu, bi, off);
            if (ov > best || (ov == best && oi < bi)) { best = ov; bi = oi; }
        }
        best = __shfl_sync(0xffffffffu, best, 0);
        bi   = __shfl_sync(0xffffffffu, bi, 0);

        float second = -3.4e38f;
#pragma unroll
        for (int i = 0; i < 10; i++) {
            const int v = i * 32 + lane;
            if (v != bi) second = fmaxf(second, vals[i]);
        }
#pragma unroll
        for (int off = 16; off; off >>= 1)
            second = fmaxf(second, __shfl_xor_sync(0xffffffffu, second, off));

        if (best - second < THRESH) {
            const float* xrow = x + (size_t)grow * E_;
            float ex_best = -3.4e38f;
            int   ex_bi   = V_;
            const float cut = best - THRESH;
            for (int i = 0; i < 10; i++) {
                unsigned bal = __ballot_sync(0xffffffffu, vals[i] >= cut);
                while (bal) {
                    const int j = __ffs(bal) - 1;
                    bal &= bal - 1;
                    const int vc = i * 32 + j;
                    const int c  = g * V_ + vc;
                    float s = 0.0f;
                    for (int k = lane; k < E_; k += 32)
                        s = fmaf(xrow[k], W[(size_t)k * GV_ + c], s);
#pragma unroll
                    for (int off = 16; off; off >>= 1)
                        s += __shfl_xor_sync(0xffffffffu, s, off);
                    float uu = fmaf(urow[vc], kA, kB);
                    float ex = s + brow[vc] + (-logf(-logf(uu)));
                    if (ex > ex_best || (ex == ex_best && vc < ex_bi)) {
                        ex_best = ex;
                        ex_bi   = vc;
                    }
                }
            }
            bi = ex_bi;
        }

        if (lane == 0) {
            const int b = grow >> 11;        // / N_
            atomicAdd(&g_counts[(b * G_ + g) * V_ + bi], 1);
        }

        const float4* cb = (const float4*)(codebook + ((size_t)(g * V_ + bi)) * D_);
        float4*       op = (float4*)(out + ((size_t)grow * 2 + g) * D_);
#pragma unroll
        for (int i = 0; i < 4; i++)
            op[i * 32 + lane] = cb[i * 32 + lane];
    }
}

// ---------------------------------------------------------------------------
// Kernel 3: entropy from histograms
// ---------------------------------------------------------------------------
__global__ void entropy_kernel(float* __restrict__ out, int out_size) {
    const int w    = threadIdx.x >> 5;
    const int lane = threadIdx.x & 31;
    const int* c = g_counts + w * V_;

    float cv[10];
    float m = -3.4e38f;
#pragma unroll
    for (int i = 0; i < 10; i++) {
        cv[i] = (float)c[lane + i * 32];
        m = fmaxf(m, cv[i]);
    }
#pragma unroll
    for (int off = 16; off; off >>= 1)
        m = fmaxf(m, __shfl_xor_sync(0xffffffffu, m, off));

    float s = 0.0f;
#pragma unroll
    for (int i = 0; i < 10; i++)
        s += expf(cv[i] - m);
#pragma unroll
    for (int off = 16; off; off >>= 1)
        s += __shfl_xor_sync(0xffffffffu, s, off);

    float ent = 0.0f;
#pragma unroll
    for (int i = 0; i < 10; i++) {
        float p = expf(cv[i] - m) / s;
        ent += p * logf(p + 1e-8f);
    }
#pragma unroll
    for (int off = 16; off; off >>= 1)
        ent += __shfl_xor_sync(0xffffffffu, ent, off);

    __shared__ float part[32];
    if (lane == 0) part[w] = ent;
    __syncthreads();
    if (threadIdx.x == 0) {
        float t = 0.0f;
#pragma unroll
        for (int i = 0; i < 32; i++)
            t += part[i];
        out[out_size - 1] = -t / (float)(G_ * V_);
    }
}

// ---------------------------------------------------------------------------
extern "C" void kernel_launch(void* const* d_in, const int* in_sizes, int n_in,
                              void* d_out, int out_size) {
    const float* x        = (const float*)d_in[0];
    const float* u        = (const float*)d_in[1];
    const float* W        = (const float*)d_in[2];
    const float* bias     = (const float*)d_in[3];
    const float* codebook = (const float*)d_in[4];
    float* out = (float*)d_out;
    (void)in_sizes; (void)n_in;

    cudaFuncSetAttribute(fused_gemm_argmax_kernel,
                         cudaFuncAttributeMaxDynamicSharedMemorySize, SMEM_DYN);

    zero_counts_kernel<<<(B_ * G_ * V_ + 255) / 256, 256>>>();

    convert_x_kernel<<<(M_ * E_ / 4 + 255) / 256, 256>>>(x);
    convert_w_kernel<<<(GV_ * E_ + 255) / 256, 256>>>(W);

    fused_gemm_argmax_kernel<<<M_ / 64, 512, SMEM_DYN>>>(x, u, W, bias, codebook, out);

    entropy_kernel<<<1, 1024>>>(out, out_size);
}

// round 13
// speedup vs baseline: 1.4620x; 1.3813x over previous
#include <cuda_runtime.h>
#include <cuda_bf16.h>
#include <math.h>

// Problem constants
#define B_  16
#define N_  2048
#define E_  1024
#define G_  2
#define V_  320
#define D_  512
#define GV_ 640
#define M_  (B_ * N_)
#define ROWS_ (M_ * G_)

#define BK   32
#define NIT  (E_ / BK)       // 32
#define APITCH 40            // bf16 elems per smem row (80B, ldsm conflict-free)
#define THRESH 0.05f

// Dynamic smem: 3 stages x (A 256x40 + B 128x40) bf16
#define STG_BYTES  30720
#define SMEM_TOTAL 92160

// Device scratch (sanctioned: __device__ globals)
__device__ __nv_bfloat16 g_xb[(size_t)M_ * E_];   // x bf16
__device__ __nv_bfloat16 g_wt[(size_t)GV_ * E_];  // W^T bf16 [n][k]
__device__ __nv_bfloat16 g_hb[(size_t)M_ * GV_];  // logits bf16 (42 MB)
__device__ int           g_counts[B_ * G_ * V_];

// ---------------------------------------------------------------------------
// PTX helpers
// ---------------------------------------------------------------------------
__device__ __forceinline__ unsigned smem_u32(const void* p) {
    unsigned a;
    asm("{ .reg .u64 t; cvta.to.shared.u64 t, %1; cvt.u32.u64 %0, t; }"
        : "=r"(a) : "l"(p));
    return a;
}
__device__ __forceinline__ void cp_async16(unsigned dst, const void* src) {
    asm volatile("cp.async.cg.shared.global [%0], [%1], 16;" :: "r"(dst), "l"(src));
}
__device__ __forceinline__ void cp_commit() {
    asm volatile("cp.async.commit_group;" ::: "memory");
}
__device__ __forceinline__ void cp_wait0() { asm volatile("cp.async.wait_group 0;" ::: "memory"); }
__device__ __forceinline__ void cp_wait1() { asm volatile("cp.async.wait_group 1;" ::: "memory"); }

__device__ __forceinline__ void ldsm4(unsigned* r, unsigned addr) {
    asm volatile("ldmatrix.sync.aligned.m8n8.x4.shared.b16 {%0,%1,%2,%3}, [%4];"
                 : "=r"(r[0]), "=r"(r[1]), "=r"(r[2]), "=r"(r[3]) : "r"(addr));
}
__device__ __forceinline__ void mma16816(float* c, const unsigned* a,
                                         unsigned b0, unsigned b1) {
    asm volatile(
        "mma.sync.aligned.m16n8k16.row.col.f32.bf16.bf16.f32 "
        "{%0,%1,%2,%3}, {%4,%5,%6,%7}, {%8,%9}, {%0,%1,%2,%3};"
        : "+f"(c[0]), "+f"(c[1]), "+f"(c[2]), "+f"(c[3])
        : "r"(a[0]), "r"(a[1]), "r"(a[2]), "r"(a[3]), "r"(b0), "r"(b1));
}

// Issue one k-tile: 2 A rows + 1 B row chunk per thread (3 x 16B)
__device__ __forceinline__ void issue_tile(unsigned dA, unsigned dB,
                                           const __nv_bfloat16* ag,
                                           const __nv_bfloat16* bg) {
    cp_async16(dA,         ag);
    cp_async16(dA + 10240, ag + (size_t)128 * E_);   // rows +128
    cp_async16(dB,         bg);
    cp_commit();
}

// ---------------------------------------------------------------------------
// Kernel 1 (merged prep): zero counts + convert W^T + convert x.
// Streaming-bound; the guarded extra work rides along free.
// ---------------------------------------------------------------------------
__global__ __launch_bounds__(256)
void prep_kernel(const float* __restrict__ x, const float* __restrict__ W) {
    const int i = blockIdx.x * blockDim.x + threadIdx.x;

    if (i < B_ * G_ * V_) g_counts[i] = 0;

    if (i < GV_ * E_) {
        const int n = i >> 10;
        const int k = i & 1023;
        g_wt[i] = __float2bfloat16(W[(size_t)k * GV_ + n]);
    }

    const int n4 = M_ * E_ / 4;
    if (i < n4) {
        float4 v = ((const float4*)x)[i];
        union { __nv_bfloat16 h[4]; uint2 u; } pk;
        pk.h[0] = __float2bfloat16(v.x);
        pk.h[1] = __float2bfloat16(v.y);
        pk.h[2] = __float2bfloat16(v.z);
        pk.h[3] = __float2bfloat16(v.w);
        ((uint2*)g_xb)[i] = pk.u;
    }
}

// ---------------------------------------------------------------------------
// Kernel 2: bf16 tensor-core GEMM h = x @ W (f32 accum, bf16 store).
// BM=256, BN=128, BK=32; 512 thr = 16 warps (4 x 4), warp tile 64x32.
// 3-stage cp.async pipeline. (R6-proven: 142 us, tensor 49.6%.)
// ---------------------------------------------------------------------------
__global__ __launch_bounds__(512, 1)
void mma_gemm_kernel() {
    extern __shared__ __align__(16) __nv_bfloat16 smem[];

    const int tid  = threadIdx.x;
    const int lane = tid & 31;
    const int wid  = tid >> 5;           // 0..15
    const int bm = blockIdx.y * 256;
    const int bn = blockIdx.x * 128;
    const int wm = (wid & 3) * 64;
    const int wn = (wid >> 2) * 32;

    const int arow  = tid >> 2;          // 0..127
    const int acoff = (tid & 3) * 8;     // 0,8,16,24

    const __nv_bfloat16* ag = g_xb + (size_t)(bm + arow) * E_ + acoff;
    const __nv_bfloat16* bg = g_wt + (size_t)(bn + arow) * E_ + acoff;

    const unsigned sBase = smem_u32(&smem[0]);
    const unsigned dA = sBase + (unsigned)(arow * APITCH + acoff) * 2u;
    const unsigned dB = sBase + 20480u + (unsigned)(arow * APITCH + acoff) * 2u;

    float acc[4][4][4];
    for (int i = 0; i < 4; i++)
        for (int j = 0; j < 4; j++)
            for (int k = 0; k < 4; k++)
                acc[i][j][k] = 0.0f;

    issue_tile(dA, dB, ag, bg);
    issue_tile(dA + STG_BYTES, dB + STG_BYTES, ag + BK, bg + BK);

    const int arow_f = wm + (lane & 15);
    const int acol_f = (lane >> 4) * 8;
    const unsigned aBase = sBase + (unsigned)(arow_f * APITCH + acol_f) * 2u;
    const int brow_f = wn + (lane & 7) + ((lane >> 4) << 3);
    const int bcol_f = ((lane >> 3) & 1) * 8;
    const unsigned bBase = sBase + 20480u + (unsigned)(brow_f * APITCH + bcol_f) * 2u;

    for (int it = 0; it < NIT; ++it) {
        const int s = it % 3;
        if (it == NIT - 1) cp_wait0(); else cp_wait1();
        __syncthreads();

        if (it + 2 < NIT) {
            const int s2 = (it + 2) % 3;
            issue_tile(dA + (unsigned)(s2 * STG_BYTES),
                       dB + (unsigned)(s2 * STG_BYTES),
                       ag + (it + 2) * BK, bg + (it + 2) * BK);
        }

        const unsigned so = (unsigned)(s * STG_BYTES);
#pragma unroll
        for (int kk = 0; kk < 2; ++kk) {
            unsigned af[4][4];
            unsigned bf[2][4];
#pragma unroll
            for (int mi = 0; mi < 4; ++mi)
                ldsm4(af[mi], aBase + so + (unsigned)(mi * 16 * APITCH + kk * 16) * 2u);
#pragma unroll
            for (int p = 0; p < 2; ++p)
                ldsm4(bf[p], bBase + so + (unsigned)(p * 16 * APITCH + kk * 16) * 2u);
#pragma unroll
            for (int mi = 0; mi < 4; ++mi) {
#pragma unroll
                for (int p = 0; p < 2; ++p) {
                    mma16816(acc[mi][2 * p],     af[mi], bf[p][0], bf[p][1]);
                    mma16816(acc[mi][2 * p + 1], af[mi], bf[p][2], bf[p][3]);
                }
            }
        }
    }

    // Epilogue: f32 acc -> bf16x2 stores
    const int cg = lane >> 2;
    const int tg = lane & 3;
#pragma unroll
    for (int mi = 0; mi < 4; ++mi) {
        const int row = bm + wm + mi * 16 + cg;
        __nv_bfloat162* o0 =
            (__nv_bfloat162*)(g_hb + (size_t)row * GV_ + bn + wn + tg * 2);
        __nv_bfloat162* o1 =
            (__nv_bfloat162*)(g_hb + (size_t)(row + 8) * GV_ + bn + wn + tg * 2);
#pragma unroll
        for (int ni = 0; ni < 4; ++ni) {
            float2 v0; v0.x = acc[mi][ni][0]; v0.y = acc[mi][ni][1];
            float2 v1; v1.x = acc[mi][ni][2]; v1.y = acc[mi][ni][3];
            o0[ni * 4] = __float22bfloat162_rn(v0);
            o1[ni * 4] = __float22bfloat162_rn(v1);
        }
    }
}

// ---------------------------------------------------------------------------
// Kernel 3: argmax + exact rescue + histogram + gather. One warp per row.
// ---------------------------------------------------------------------------
__global__ __launch_bounds__(256)
void argmax_gather_kernel(const float* __restrict__ x,
                          const float* __restrict__ u,
                          const float* __restrict__ W,
                          const float* __restrict__ bias,
                          const float* __restrict__ codebook,
                          float* __restrict__ out) {
    const int warp = (blockIdx.x * blockDim.x + threadIdx.x) >> 5;
    const int lane = threadIdx.x & 31;
    if (warp >= ROWS_) return;

    const int r    = warp;
    const int gidx = r & 1;
    const __nv_bfloat16* hrow = g_hb + (size_t)r * V_;
    const float* urow = u + (size_t)r * V_;
    const float* brow = bias + gidx * V_;

    const float kA = 1.0f - 2.0f * 1e-7f;
    const float kB = 1e-7f;

    float vals[10];
    float best = -3.4e38f;
    int   bi   = 0;
#pragma unroll
    for (int i = 0; i < 10; i++) {
        const int v = i * 32 + lane;
        float uu = fmaf(urow[v], kA, kB);
        float gn = -logf(-logf(uu));
        float val = __bfloat162float(hrow[v]) + brow[v] + gn;
        vals[i] = val;
        if (val > best) { best = val; bi = v; }
    }
#pragma unroll
    for (int off = 16; off; off >>= 1) {
        float ov = __shfl_down_sync(0xffffffffu, best, off);
        int   oi = __shfl_down_sync(0xffffffffu, bi, off);
        if (ov > best || (ov == best && oi < bi)) { best = ov; bi = oi; }
    }
    best = __shfl_sync(0xffffffffu, best, 0);
    bi   = __shfl_sync(0xffffffffu, bi, 0);

    float second = -3.4e38f;
#pragma unroll
    for (int i = 0; i < 10; i++) {
        const int v = i * 32 + lane;
        if (v != bi) second = fmaxf(second, vals[i]);
    }
#pragma unroll
    for (int off = 16; off; off >>= 1)
        second = fmaxf(second, __shfl_xor_sync(0xffffffffu, second, off));

    if (best - second < THRESH) {
        const float* xrow = x + (size_t)(r >> 1) * E_;
        float ex_best = -3.4e38f;
        int   ex_bi   = V_;
        const float cut = best - THRESH;
        for (int i = 0; i < 10; i++) {
            unsigned bal = __ballot_sync(0xffffffffu, vals[i] >= cut);
            while (bal) {
                const int j = __ffs(bal) - 1;
                bal &= bal - 1;
                const int vc = i * 32 + j;
                const int c  = gidx * V_ + vc;
                float s = 0.0f;
                for (int k = lane; k < E_; k += 32)
                    s = fmaf(xrow[k], W[(size_t)k * GV_ + c], s);
#pragma unroll
                for (int off = 16; off; off >>= 1)
                    s += __shfl_xor_sync(0xffffffffu, s, off);
                float uu = fmaf(urow[vc], kA, kB);
                float ex = s + brow[vc] + (-logf(-logf(uu)));
                if (ex > ex_best || (ex == ex_best && vc < ex_bi)) {
                    ex_best = ex;
                    ex_bi   = vc;
                }
            }
        }
        bi = ex_bi;
    }

    if (lane == 0) {
        int b = r >> 12;
        atomicAdd(&g_counts[(b * G_ + gidx) * V_ + bi], 1);
    }

    const float4* cb = (const float4*)(codebook + ((size_t)(gidx * V_ + bi)) * D_);
    float4*       op = (float4*)(out + (size_t)r * D_);
#pragma unroll
    for (int i = 0; i < 4; i++)
        op[i * 32 + lane] = cb[i * 32 + lane];
}

// ---------------------------------------------------------------------------
// Kernel 4: entropy from histograms
// ---------------------------------------------------------------------------
__global__ void entropy_kernel(float* __restrict__ out, int out_size) {
    const int w    = threadIdx.x >> 5;
    const int lane = threadIdx.x & 31;
    const int* c = g_counts + w * V_;

    float cv[10];
    float m = -3.4e38f;
#pragma unroll
    for (int i = 0; i < 10; i++) {
        cv[i] = (float)c[lane + i * 32];
        m = fmaxf(m, cv[i]);
    }
#pragma unroll
    for (int off = 16; off; off >>= 1)
        m = fmaxf(m, __shfl_xor_sync(0xffffffffu, m, off));

    float s = 0.0f;
#pragma unroll
    for (int i = 0; i < 10; i++)
        s += expf(cv[i] - m);
#pragma unroll
    for (int off = 16; off; off >>= 1)
        s += __shfl_xor_sync(0xffffffffu, s, off);

    float ent = 0.0f;
#pragma unroll
    for (int i = 0; i < 10; i++) {
        float p = expf(cv[i] - m) / s;
        ent += p * logf(p + 1e-8f);
    }
#pragma unroll
    for (int off = 16; off; off >>= 1)
        ent += __shfl_xor_sync(0xffffffffu, ent, off);

    __shared__ float part[32];
    if (lane == 0) part[w] = ent;
    __syncthreads();
    if (threadIdx.x == 0) {
        float t = 0.0f;
#pragma unroll
        for (int i = 0; i < 32; i++)
            t += part[i];
        out[out_size - 1] = -t / (float)(G_ * V_);
    }
}

// ---------------------------------------------------------------------------
extern "C" void kernel_launch(void* const* d_in, const int* in_sizes, int n_in,
                              void* d_out, int out_size) {
    const float* x        = (const float*)d_in[0];
    const float* u        = (const float*)d_in[1];
    const float* W        = (const float*)d_in[2];
    const float* bias     = (const float*)d_in[3];
    const float* codebook = (const float*)d_in[4];
    float* out = (float*)d_out;
    (void)in_sizes; (void)n_in;

    cudaFuncSetAttribute(mma_gemm_kernel,
                         cudaFuncAttributeMaxDynamicSharedMemorySize, SMEM_TOTAL);

    // One merged prep launch: zero counts + convert W + convert x
    prep_kernel<<<(M_ * E_ / 4 + 255) / 256, 256>>>(x, W);

    dim3 gg(GV_ / 128, M_ / 256);   // (5, 128)
    mma_gemm_kernel<<<gg, 512, SMEM_TOTAL>>>();

    argmax_gather_kernel<<<(ROWS_ * 32 + 255) / 256, 256>>>(x, u, W, bias, codebook, out);

    entropy_kernel<<<1, 1024>>>(out, out_size);
}

// round 14
// speedup vs baseline: 1.5276x; 1.0449x over previous
#include <cuda_runtime.h>
#include <cuda_bf16.h>
#include <math.h>

// Problem constants
#define B_  16
#define N_  2048
#define E_  1024
#define G_  2
#define V_  320
#define D_  512
#define GV_ 640
#define M_  (B_ * N_)
#define ROWS_ (M_ * G_)

#define BK   32
#define NIT  (E_ / BK)       // 32
#define APITCH 40            // bf16 elems per smem row (80B, ldsm conflict-free)
#define THRESH 0.05f

// Dynamic smem: 3 stages x (A 256x40 + B 128x40) bf16
#define STG_BYTES  30720
#define SMEM_TOTAL 92160

// Device scratch (sanctioned: __device__ globals)
__device__ __nv_bfloat16 g_xb[(size_t)M_ * E_];   // x bf16
__device__ __nv_bfloat16 g_wt[(size_t)GV_ * E_];  // W^T bf16 [n][k]
__device__ __nv_bfloat16 g_hb[(size_t)M_ * GV_];  // logits bf16 (42 MB)
__device__ int           g_counts[B_ * G_ * V_];

// ---------------------------------------------------------------------------
// PTX helpers
// ---------------------------------------------------------------------------
__device__ __forceinline__ unsigned smem_u32(const void* p) {
    unsigned a;
    asm("{ .reg .u64 t; cvta.to.shared.u64 t, %1; cvt.u32.u64 %0, t; }"
        : "=r"(a) : "l"(p));
    return a;
}
__device__ __forceinline__ void cp_async16(unsigned dst, const void* src) {
    asm volatile("cp.async.cg.shared.global [%0], [%1], 16;" :: "r"(dst), "l"(src));
}
__device__ __forceinline__ void cp_commit() {
    asm volatile("cp.async.commit_group;" ::: "memory");
}
__device__ __forceinline__ void cp_wait0() { asm volatile("cp.async.wait_group 0;" ::: "memory"); }
__device__ __forceinline__ void cp_wait1() { asm volatile("cp.async.wait_group 1;" ::: "memory"); }

__device__ __forceinline__ void ldsm4(unsigned* r, unsigned addr) {
    asm volatile("ldmatrix.sync.aligned.m8n8.x4.shared.b16 {%0,%1,%2,%3}, [%4];"
                 : "=r"(r[0]), "=r"(r[1]), "=r"(r[2]), "=r"(r[3]) : "r"(addr));
}
__device__ __forceinline__ void mma16816(float* c, const unsigned* a,
                                         unsigned b0, unsigned b1) {
    asm volatile(
        "mma.sync.aligned.m16n8k16.row.col.f32.bf16.bf16.f32 "
        "{%0,%1,%2,%3}, {%4,%5,%6,%7}, {%8,%9}, {%0,%1,%2,%3};"
        : "+f"(c[0]), "+f"(c[1]), "+f"(c[2]), "+f"(c[3])
        : "r"(a[0]), "r"(a[1]), "r"(a[2]), "r"(a[3]), "r"(b0), "r"(b1));
}

// Issue one k-tile: 2 A rows + 1 B row chunk per thread (3 x 16B)
__device__ __forceinline__ void issue_tile(unsigned dA, unsigned dB,
                                           const __nv_bfloat16* ag,
                                           const __nv_bfloat16* bg) {
    cp_async16(dA,         ag);
    cp_async16(dA + 10240, ag + (size_t)128 * E_);   // rows +128
    cp_async16(dB,         bg);
    cp_commit();
}

// ---------------------------------------------------------------------------
// Kernel 1 (merged prep): zero counts + convert W^T + convert x.
// ---------------------------------------------------------------------------
__global__ __launch_bounds__(256)
void prep_kernel(const float* __restrict__ x, const float* __restrict__ W) {
    const int i = blockIdx.x * blockDim.x + threadIdx.x;

    if (i < B_ * G_ * V_) g_counts[i] = 0;

    if (i < GV_ * E_) {
        const int n = i >> 10;
        const int k = i & 1023;
        g_wt[i] = __float2bfloat16(W[(size_t)k * GV_ + n]);
    }

    const int n4 = M_ * E_ / 4;
    if (i < n4) {
        float4 v = ((const float4*)x)[i];
        union { __nv_bfloat16 h[4]; uint2 u; } pk;
        pk.h[0] = __float2bfloat16(v.x);
        pk.h[1] = __float2bfloat16(v.y);
        pk.h[2] = __float2bfloat16(v.z);
        pk.h[3] = __float2bfloat16(v.w);
        ((uint2*)g_xb)[i] = pk.u;
    }
}

// ---------------------------------------------------------------------------
// Kernel 2: bf16 tensor-core GEMM h = x @ W (f32 accum, bf16 store).
// BM=256, BN=128, BK=32; 512 thr = 16 warps (4 x 4), warp tile 64x32.
// 3-stage cp.async pipeline. (R6-proven: 142 us, tensor 49.6% = pipe cap.)
// ---------------------------------------------------------------------------
__global__ __launch_bounds__(512, 1)
void mma_gemm_kernel() {
    extern __shared__ __align__(16) __nv_bfloat16 smem[];

    const int tid  = threadIdx.x;
    const int lane = tid & 31;
    const int wid  = tid >> 5;           // 0..15
    const int bm = blockIdx.y * 256;
    const int bn = blockIdx.x * 128;
    const int wm = (wid & 3) * 64;
    const int wn = (wid >> 2) * 32;

    const int arow  = tid >> 2;          // 0..127
    const int acoff = (tid & 3) * 8;     // 0,8,16,24

    const __nv_bfloat16* ag = g_xb + (size_t)(bm + arow) * E_ + acoff;
    const __nv_bfloat16* bg = g_wt + (size_t)(bn + arow) * E_ + acoff;

    const unsigned sBase = smem_u32(&smem[0]);
    const unsigned dA = sBase + (unsigned)(arow * APITCH + acoff) * 2u;
    const unsigned dB = sBase + 20480u + (unsigned)(arow * APITCH + acoff) * 2u;

    float acc[4][4][4];
    for (int i = 0; i < 4; i++)
        for (int j = 0; j < 4; j++)
            for (int k = 0; k < 4; k++)
                acc[i][j][k] = 0.0f;

    issue_tile(dA, dB, ag, bg);
    issue_tile(dA + STG_BYTES, dB + STG_BYTES, ag + BK, bg + BK);

    const int arow_f = wm + (lane & 15);
    const int acol_f = (lane >> 4) * 8;
    const unsigned aBase = sBase + (unsigned)(arow_f * APITCH + acol_f) * 2u;
    const int brow_f = wn + (lane & 7) + ((lane >> 4) << 3);
    const int bcol_f = ((lane >> 3) & 1) * 8;
    const unsigned bBase = sBase + 20480u + (unsigned)(brow_f * APITCH + bcol_f) * 2u;

    for (int it = 0; it < NIT; ++it) {
        const int s = it % 3;
        if (it == NIT - 1) cp_wait0(); else cp_wait1();
        __syncthreads();

        if (it + 2 < NIT) {
            const int s2 = (it + 2) % 3;
            issue_tile(dA + (unsigned)(s2 * STG_BYTES),
                       dB + (unsigned)(s2 * STG_BYTES),
                       ag + (it + 2) * BK, bg + (it + 2) * BK);
        }

        const unsigned so = (unsigned)(s * STG_BYTES);
#pragma unroll
        for (int kk = 0; kk < 2; ++kk) {
            unsigned af[4][4];
            unsigned bf[2][4];
#pragma unroll
            for (int mi = 0; mi < 4; ++mi)
                ldsm4(af[mi], aBase + so + (unsigned)(mi * 16 * APITCH + kk * 16) * 2u);
#pragma unroll
            for (int p = 0; p < 2; ++p)
                ldsm4(bf[p], bBase + so + (unsigned)(p * 16 * APITCH + kk * 16) * 2u);
#pragma unroll
            for (int mi = 0; mi < 4; ++mi) {
#pragma unroll
                for (int p = 0; p < 2; ++p) {
                    mma16816(acc[mi][2 * p],     af[mi], bf[p][0], bf[p][1]);
                    mma16816(acc[mi][2 * p + 1], af[mi], bf[p][2], bf[p][3]);
                }
            }
        }
    }

    // Epilogue: f32 acc -> bf16x2 stores
    const int cg = lane >> 2;
    const int tg = lane & 3;
#pragma unroll
    for (int mi = 0; mi < 4; ++mi) {
        const int row = bm + wm + mi * 16 + cg;
        __nv_bfloat162* o0 =
            (__nv_bfloat162*)(g_hb + (size_t)row * GV_ + bn + wn + tg * 2);
        __nv_bfloat162* o1 =
            (__nv_bfloat162*)(g_hb + (size_t)(row + 8) * GV_ + bn + wn + tg * 2);
#pragma unroll
        for (int ni = 0; ni < 4; ++ni) {
            float2 v0; v0.x = acc[mi][ni][0]; v0.y = acc[mi][ni][1];
            float2 v1; v1.x = acc[mi][ni][2]; v1.y = acc[mi][ni][3];
            o0[ni * 4] = __float22bfloat162_rn(v0);
            o1[ni * 4] = __float22bfloat162_rn(v1);
        }
    }
}

// ---------------------------------------------------------------------------
// Kernel 3: argmax + exact rescue + histogram + gather. One warp per row.
// Scan phase uses __logf (MUFU-based fast log, abs err <= ~1e-5 here);
// accept margin THRESH covers 2*(bf16 h-noise 0.019 + fast-log 1e-5) = 0.038.
// Rescue recomputes candidates with exact fp32 logf -> decisions identical
// to the fp32 reference.
// ---------------------------------------------------------------------------
__global__ __launch_bounds__(256)
void argmax_gather_kernel(const float* __restrict__ x,
                          const float* __restrict__ u,
                          const float* __restrict__ W,
                          const float* __restrict__ bias,
                          const float* __restrict__ codebook,
                          float* __restrict__ out) {
    const int warp = (blockIdx.x * blockDim.x + threadIdx.x) >> 5;
    const int lane = threadIdx.x & 31;
    if (warp >= ROWS_) return;

    const int r    = warp;
    const int gidx = r & 1;
    const __nv_bfloat16* hrow = g_hb + (size_t)r * V_;
    const float* urow = u + (size_t)r * V_;
    const float* brow = bias + gidx * V_;

    const float kA = 1.0f - 2.0f * 1e-7f;
    const float kB = 1e-7f;

    float vals[10];
    float best = -3.4e38f;
    int   bi   = 0;
#pragma unroll
    for (int i = 0; i < 10; i++) {
        const int v = i * 32 + lane;
        float uu = fmaf(urow[v], kA, kB);
        float gn = -__logf(-__logf(uu));          // fast log in scan
        float val = __bfloat162float(hrow[v]) + brow[v] + gn;
        vals[i] = val;
        if (val > best) { best = val; bi = v; }
    }
#pragma unroll
    for (int off = 16; off; off >>= 1) {
        float ov = __shfl_down_sync(0xffffffffu, best, off);
        int   oi = __shfl_down_sync(0xffffffffu, bi, off);
        if (ov > best || (ov == best && oi < bi)) { best = ov; bi = oi; }
    }
    best = __shfl_sync(0xffffffffu, best, 0);
    bi   = __shfl_sync(0xffffffffu, bi, 0);

    float second = -3.4e38f;
#pragma unroll
    for (int i = 0; i < 10; i++) {
        const int v = i * 32 + lane;
        if (v != bi) second = fmaxf(second, vals[i]);
    }
#pragma unroll
    for (int off = 16; off; off >>= 1)
        second = fmaxf(second, __shfl_xor_sync(0xffffffffu, second, off));

    if (best - second < THRESH) {
        const float* xrow = x + (size_t)(r >> 1) * E_;
        float ex_best = -3.4e38f;
        int   ex_bi   = V_;
        const float cut = best - THRESH;
        for (int i = 0; i < 10; i++) {
            unsigned bal = __ballot_sync(0xffffffffu, vals[i] >= cut);
            while (bal) {
                const int j = __ffs(bal) - 1;
                bal &= bal - 1;
                const int vc = i * 32 + j;
                const int c  = gidx * V_ + vc;
                float s = 0.0f;
                for (int k = lane; k < E_; k += 32)
                    s = fmaf(xrow[k], W[(size_t)k * GV_ + c], s);
#pragma unroll
                for (int off = 16; off; off >>= 1)
                    s += __shfl_xor_sync(0xffffffffu, s, off);
                float uu = fmaf(urow[vc], kA, kB);
                float ex = s + brow[vc] + (-logf(-logf(uu)));   // exact log
                if (ex > ex_best || (ex == ex_best && vc < ex_bi)) {
                    ex_best = ex;
                    ex_bi   = vc;
                }
            }
        }
        bi = ex_bi;
    }

    if (lane == 0) {
        int b = r >> 12;
        atomicAdd(&g_counts[(b * G_ + gidx) * V_ + bi], 1);
    }

    const float4* cb = (const float4*)(codebook + ((size_t)(gidx * V_ + bi)) * D_);
    float4*       op = (float4*)(out + (size_t)r * D_);
#pragma unroll
    for (int i = 0; i < 4; i++)
        op[i * 32 + lane] = cb[i * 32 + lane];
}

// ---------------------------------------------------------------------------
// Kernel 4: entropy from histograms
// ---------------------------------------------------------------------------
__global__ void entropy_kernel(float* __restrict__ out, int out_size) {
    const int w    = threadIdx.x >> 5;
    const int lane = threadIdx.x & 31;
    const int* c = g_counts + w * V_;

    float cv[10];
    float m = -3.4e38f;
#pragma unroll
    for (int i = 0; i < 10; i++) {
        cv[i] = (float)c[lane + i * 32];
        m = fmaxf(m, cv[i]);
    }
#pragma unroll
    for (int off = 16; off; off >>= 1)
        m = fmaxf(m, __shfl_xor_sync(0xffffffffu, m, off));

    float s = 0.0f;
#pragma unroll
    for (int i = 0; i < 10; i++)
        s += expf(cv[i] - m);
#pragma unroll
    for (int off = 16; off; off >>= 1)
        s += __shfl_xor_sync(0xffffffffu, s, off);

    float ent = 0.0f;
#pragma unroll
    for (int i = 0; i < 10; i++) {
        float p = expf(cv[i] - m) / s;
        ent += p * logf(p + 1e-8f);
    }
#pragma unroll
    for (int off = 16; off; off >>= 1)
        ent += __shfl_xor_sync(0xffffffffu, ent, off);

    __shared__ float part[32];
    if (lane == 0) part[w] = ent;
    __syncthreads();
    if (threadIdx.x == 0) {
        float t = 0.0f;
#pragma unroll
        for (int i = 0; i < 32; i++)
            t += part[i];
        out[out_size - 1] = -t / (float)(G_ * V_);
    }
}

// ---------------------------------------------------------------------------
extern "C" void kernel_launch(void* const* d_in, const int* in_sizes, int n_in,
                              void* d_out, int out_size) {
    const float* x        = (const float*)d_in[0];
    const float* u        = (const float*)d_in[1];
    const float* W        = (const float*)d_in[2];
    const float* bias     = (const float*)d_in[3];
    const float* codebook = (const float*)d_in[4];
    float* out = (float*)d_out;
    (void)in_sizes; (void)n_in;

    cudaFuncSetAttribute(mma_gemm_kernel,
                         cudaFuncAttributeMaxDynamicSharedMemorySize, SMEM_TOTAL);

    prep_kernel<<<(M_ * E_ / 4 + 255) / 256, 256>>>(x, W);

    dim3 gg(GV_ / 128, M_ / 256);   // (5, 128)
    mma_gemm_kernel<<<gg, 512, SMEM_TOTAL>>>();

    argmax_gather_kernel<<<(ROWS_ * 32 + 255) / 256, 256>>>(x, u, W, bias, codebook, out);

    entropy_kernel<<<1, 1024>>>(out, out_size);
}

// round 15
// speedup vs baseline: 1.6157x; 1.0577x over previous
#include <cuda_runtime.h>
#include <cuda_bf16.h>
#include <math.h>

// Problem constants
#define B_  16
#define N_  2048
#define E_  1024
#define G_  2
#define V_  320
#define D_  512
#define GV_ 640
#define M_  (B_ * N_)
#define ROWS_ (M_ * G_)

#define BK   32
#define NIT  (E_ / BK)       // 32
#define APITCH 40            // bf16 elems per smem row (80B, ldsm conflict-free)
#define THRESH 0.05f

// Dynamic smem: 3 stages x (A 256x40 + B 128x40) bf16
#define STG_BYTES  30720
#define SMEM_TOTAL 92160

// Device scratch (sanctioned: __device__ globals)
__device__ __nv_bfloat16 g_xb[(size_t)M_ * E_];   // x bf16
__device__ __nv_bfloat16 g_wt[(size_t)GV_ * E_];  // W^T bf16 [n][k]
__device__ float         g_wtf[(size_t)GV_ * E_]; // W^T fp32 [n][k] (rescue)
__device__ __nv_bfloat16 g_hb[(size_t)M_ * GV_];  // logits bf16 (42 MB)
__device__ int           g_counts[B_ * G_ * V_];

// ---------------------------------------------------------------------------
// PTX helpers
// ---------------------------------------------------------------------------
__device__ __forceinline__ unsigned smem_u32(const void* p) {
    unsigned a;
    asm("{ .reg .u64 t; cvta.to.shared.u64 t, %1; cvt.u32.u64 %0, t; }"
        : "=r"(a) : "l"(p));
    return a;
}
__device__ __forceinline__ void cp_async16(unsigned dst, const void* src) {
    asm volatile("cp.async.cg.shared.global [%0], [%1], 16;" :: "r"(dst), "l"(src));
}
__device__ __forceinline__ void cp_commit() {
    asm volatile("cp.async.commit_group;" ::: "memory");
}
__device__ __forceinline__ void cp_wait0() { asm volatile("cp.async.wait_group 0;" ::: "memory"); }
__device__ __forceinline__ void cp_wait1() { asm volatile("cp.async.wait_group 1;" ::: "memory"); }

__device__ __forceinline__ void ldsm4(unsigned* r, unsigned addr) {
    asm volatile("ldmatrix.sync.aligned.m8n8.x4.shared.b16 {%0,%1,%2,%3}, [%4];"
                 : "=r"(r[0]), "=r"(r[1]), "=r"(r[2]), "=r"(r[3]) : "r"(addr));
}
__device__ __forceinline__ void mma16816(float* c, const unsigned* a,
                                         unsigned b0, unsigned b1) {
    asm volatile(
        "mma.sync.aligned.m16n8k16.row.col.f32.bf16.bf16.f32 "
        "{%0,%1,%2,%3}, {%4,%5,%6,%7}, {%8,%9}, {%0,%1,%2,%3};"
        : "+f"(c[0]), "+f"(c[1]), "+f"(c[2]), "+f"(c[3])
        : "r"(a[0]), "r"(a[1]), "r"(a[2]), "r"(a[3]), "r"(b0), "r"(b1));
}

// Issue one k-tile: 2 A rows + 1 B row chunk per thread (3 x 16B)
__device__ __forceinline__ void issue_tile(unsigned dA, unsigned dB,
                                           const __nv_bfloat16* ag,
                                           const __nv_bfloat16* bg) {
    cp_async16(dA,         ag);
    cp_async16(dA + 10240, ag + (size_t)128 * E_);   // rows +128
    cp_async16(dB,         bg);
    cp_commit();
}

// ---------------------------------------------------------------------------
// Kernel 1 (merged prep): zero counts + convert W^T (bf16 + fp32) + convert x.
// ---------------------------------------------------------------------------
__global__ __launch_bounds__(256)
void prep_kernel(const float* __restrict__ x, const float* __restrict__ W) {
    const int i = blockIdx.x * blockDim.x + threadIdx.x;

    if (i < B_ * G_ * V_) g_counts[i] = 0;

    if (i < GV_ * E_) {
        const int n = i >> 10;
        const int k = i & 1023;
        const float w = W[(size_t)k * GV_ + n];
        g_wt[i]  = __float2bfloat16(w);
        g_wtf[i] = w;
    }

    const int n4 = M_ * E_ / 4;
    if (i < n4) {
        float4 v = ((const float4*)x)[i];
        union { __nv_bfloat16 h[4]; uint2 u; } pk;
        pk.h[0] = __float2bfloat16(v.x);
        pk.h[1] = __float2bfloat16(v.y);
        pk.h[2] = __float2bfloat16(v.z);
        pk.h[3] = __float2bfloat16(v.w);
        ((uint2*)g_xb)[i] = pk.u;
    }
}

// ---------------------------------------------------------------------------
// Kernel 2: bf16 tensor-core GEMM h = x @ W (f32 accum, bf16 store).
// BM=256, BN=128, BK=32; 512 thr = 16 warps (4 x 4), warp tile 64x32.
// 3-stage cp.async pipeline. (R6-proven: 142 us, tensor 49.6% = pipe cap.)
// ---------------------------------------------------------------------------
__global__ __launch_bounds__(512, 1)
void mma_gemm_kernel() {
    extern __shared__ __align__(16) __nv_bfloat16 smem[];

    const int tid  = threadIdx.x;
    const int lane = tid & 31;
    const int wid  = tid >> 5;           // 0..15
    const int bm = blockIdx.y * 256;
    const int bn = blockIdx.x * 128;
    const int wm = (wid & 3) * 64;
    const int wn = (wid >> 2) * 32;

    const int arow  = tid >> 2;          // 0..127
    const int acoff = (tid & 3) * 8;     // 0,8,16,24

    const __nv_bfloat16* ag = g_xb + (size_t)(bm + arow) * E_ + acoff;
    const __nv_bfloat16* bg = g_wt + (size_t)(bn + arow) * E_ + acoff;

    const unsigned sBase = smem_u32(&smem[0]);
    const unsigned dA = sBase + (unsigned)(arow * APITCH + acoff) * 2u;
    const unsigned dB = sBase + 20480u + (unsigned)(arow * APITCH + acoff) * 2u;

    float acc[4][4][4];
    for (int i = 0; i < 4; i++)
        for (int j = 0; j < 4; j++)
            for (int k = 0; k < 4; k++)
                acc[i][j][k] = 0.0f;

    issue_tile(dA, dB, ag, bg);
    issue_tile(dA + STG_BYTES, dB + STG_BYTES, ag + BK, bg + BK);

    const int arow_f = wm + (lane & 15);
    const int acol_f = (lane >> 4) * 8;
    const unsigned aBase = sBase + (unsigned)(arow_f * APITCH + acol_f) * 2u;
    const int brow_f = wn + (lane & 7) + ((lane >> 4) << 3);
    const int bcol_f = ((lane >> 3) & 1) * 8;
    const unsigned bBase = sBase + 20480u + (unsigned)(brow_f * APITCH + bcol_f) * 2u;

    for (int it = 0; it < NIT; ++it) {
        const int s = it % 3;
        if (it == NIT - 1) cp_wait0(); else cp_wait1();
        __syncthreads();

        if (it + 2 < NIT) {
            const int s2 = (it + 2) % 3;
            issue_tile(dA + (unsigned)(s2 * STG_BYTES),
                       dB + (unsigned)(s2 * STG_BYTES),
                       ag + (it + 2) * BK, bg + (it + 2) * BK);
        }

        const unsigned so = (unsigned)(s * STG_BYTES);
#pragma unroll
        for (int kk = 0; kk < 2; ++kk) {
            unsigned af[4][4];
            unsigned bf[2][4];
#pragma unroll
            for (int mi = 0; mi < 4; ++mi)
                ldsm4(af[mi], aBase + so + (unsigned)(mi * 16 * APITCH + kk * 16) * 2u);
#pragma unroll
            for (int p = 0; p < 2; ++p)
                ldsm4(bf[p], bBase + so + (unsigned)(p * 16 * APITCH + kk * 16) * 2u);
#pragma unroll
            for (int mi = 0; mi < 4; ++mi) {
#pragma unroll
                for (int p = 0; p < 2; ++p) {
                    mma16816(acc[mi][2 * p],     af[mi], bf[p][0], bf[p][1]);
                    mma16816(acc[mi][2 * p + 1], af[mi], bf[p][2], bf[p][3]);
                }
            }
        }
    }

    // Epilogue: f32 acc -> bf16x2 stores
    const int cg = lane >> 2;
    const int tg = lane & 3;
#pragma unroll
    for (int mi = 0; mi < 4; ++mi) {
        const int row = bm + wm + mi * 16 + cg;
        __nv_bfloat162* o0 =
            (__nv_bfloat162*)(g_hb + (size_t)row * GV_ + bn + wn + tg * 2);
        __nv_bfloat162* o1 =
            (__nv_bfloat162*)(g_hb + (size_t)(row + 8) * GV_ + bn + wn + tg * 2);
#pragma unroll
        for (int ni = 0; ni < 4; ++ni) {
            float2 v0; v0.x = acc[mi][ni][0]; v0.y = acc[mi][ni][1];
            float2 v1; v1.x = acc[mi][ni][2]; v1.y = acc[mi][ni][3];
            o0[ni * 4] = __float22bfloat162_rn(v0);
            o1[ni * 4] = __float22bfloat162_rn(v1);
        }
    }
}

// ---------------------------------------------------------------------------
// Kernel 3: argmax + exact rescue + histogram + gather. One warp per row.
// Scan: __logf (MUFU). Rescue: exact fp32 logf + float4 dot over contiguous
// x row and fp32 W^T row (MLP 16 -> no straggler tail).
// ---------------------------------------------------------------------------
__global__ __launch_bounds__(256)
void argmax_gather_kernel(const float* __restrict__ x,
                          const float* __restrict__ u,
                          const float* __restrict__ bias,
                          const float* __restrict__ codebook,
                          float* __restrict__ out) {
    const int warp = (blockIdx.x * blockDim.x + threadIdx.x) >> 5;
    const int lane = threadIdx.x & 31;
    if (warp >= ROWS_) return;

    const int r    = warp;
    const int gidx = r & 1;
    const __nv_bfloat16* hrow = g_hb + (size_t)r * V_;
    const float* urow = u + (size_t)r * V_;
    const float* brow = bias + gidx * V_;

    const float kA = 1.0f - 2.0f * 1e-7f;
    const float kB = 1e-7f;

    float vals[10];
    float best = -3.4e38f;
    int   bi   = 0;
#pragma unroll
    for (int i = 0; i < 10; i++) {
        const int v = i * 32 + lane;
        float uu = fmaf(urow[v], kA, kB);
        float gn = -__logf(-__logf(uu));          // fast log in scan
        float val = __bfloat162float(hrow[v]) + brow[v] + gn;
        vals[i] = val;
        if (val > best) { best = val; bi = v; }
    }
#pragma unroll
    for (int off = 16; off; off >>= 1) {
        float ov = __shfl_down_sync(0xffffffffu, best, off);
        int   oi = __shfl_down_sync(0xffffffffu, bi, off);
        if (ov > best || (ov == best && oi < bi)) { best = ov; bi = oi; }
    }
    best = __shfl_sync(0xffffffffu, best, 0);
    bi   = __shfl_sync(0xffffffffu, bi, 0);

    float second = -3.4e38f;
#pragma unroll
    for (int i = 0; i < 10; i++) {
        const int v = i * 32 + lane;
        if (v != bi) second = fmaxf(second, vals[i]);
    }
#pragma unroll
    for (int off = 16; off; off >>= 1)
        second = fmaxf(second, __shfl_xor_sync(0xffffffffu, second, off));

    if (best - second < THRESH) {
        const float4* xr4 = (const float4*)(x + (size_t)(r >> 1) * E_);
        float ex_best = -3.4e38f;
        int   ex_bi   = V_;
        const float cut = best - THRESH;
        for (int i = 0; i < 10; i++) {
            unsigned bal = __ballot_sync(0xffffffffu, vals[i] >= cut);
            while (bal) {
                const int j = __ffs(bal) - 1;
                bal &= bal - 1;
                const int vc = i * 32 + j;
                const float4* wr4 =
                    (const float4*)(g_wtf + (size_t)(gidx * V_ + vc) * E_);
                float s0 = 0.0f, s1 = 0.0f, s2 = 0.0f, s3 = 0.0f;
#pragma unroll
                for (int k4 = lane; k4 < 256; k4 += 32) {   // 8 iters, MLP 16
                    float4 xa = xr4[k4];
                    float4 wa = wr4[k4];
                    s0 = fmaf(xa.x, wa.x, s0);
                    s1 = fmaf(xa.y, wa.y, s1);
                    s2 = fmaf(xa.z, wa.z, s2);
                    s3 = fmaf(xa.w, wa.w, s3);
                }
                float s = (s0 + s1) + (s2 + s3);
#pragma unroll
                for (int off = 16; off; off >>= 1)
                    s += __shfl_xor_sync(0xffffffffu, s, off);
                float uu = fmaf(urow[vc], kA, kB);
                float ex = s + brow[vc] + (-logf(-logf(uu)));   // exact log
                if (ex > ex_best || (ex == ex_best && vc < ex_bi)) {
                    ex_best = ex;
                    ex_bi   = vc;
                }
            }
        }
        bi = ex_bi;
    }

    if (lane == 0) {
        int b = r >> 12;
        atomicAdd(&g_counts[(b * G_ + gidx) * V_ + bi], 1);
    }

    const float4* cb = (const float4*)(codebook + ((size_t)(gidx * V_ + bi)) * D_);
    float4*       op = (float4*)(out + (size_t)r * D_);
#pragma unroll
    for (int i = 0; i < 4; i++)
        op[i * 32 + lane] = cb[i * 32 + lane];
}

// ---------------------------------------------------------------------------
// Kernel 4: entropy from histograms
// ---------------------------------------------------------------------------
__global__ void entropy_kernel(float* __restrict__ out, int out_size) {
    const int w    = threadIdx.x >> 5;
    const int lane = threadIdx.x & 31;
    const int* c = g_counts + w * V_;

    float cv[10];
    float m = -3.4e38f;
#pragma unroll
    for (int i = 0; i < 10; i++) {
        cv[i] = (float)c[lane + i * 32];
        m = fmaxf(m, cv[i]);
    }
#pragma unroll
    for (int off = 16; off; off >>= 1)
        m = fmaxf(m, __shfl_xor_sync(0xffffffffu, m, off));

    float s = 0.0f;
#pragma unroll
    for (int i = 0; i < 10; i++)
        s += expf(cv[i] - m);
#pragma unroll
    for (int off = 16; off; off >>= 1)
        s += __shfl_xor_sync(0xffffffffu, s, off);

    float ent = 0.0f;
#pragma unroll
    for (int i = 0; i < 10; i++) {
        float p = expf(cv[i] - m) / s;
        ent += p * logf(p + 1e-8f);
    }
#pragma unroll
    for (int off = 16; off; off >>= 1)
        ent += __shfl_xor_sync(0xffffffffu, ent, off);

    __shared__ float part[32];
    if (lane == 0) part[w] = ent;
    __syncthreads();
    if (threadIdx.x == 0) {
        float t = 0.0f;
#pragma unroll
        for (int i = 0; i < 32; i++)
            t += part[i];
        out[out_size - 1] = -t / (float)(G_ * V_);
    }
}

// ---------------------------------------------------------------------------
extern "C" void kernel_launch(void* const* d_in, const int* in_sizes, int n_in,
                              void* d_out, int out_size) {
    const float* x        = (const float*)d_in[0];
    const float* u        = (const float*)d_in[1];
    const float* W        = (const float*)d_in[2];
    const float* bias     = (const float*)d_in[3];
    const float* codebook = (const float*)d_in[4];
    float* out = (float*)d_out;
    (void)in_sizes; (void)n_in;

    cudaFuncSetAttribute(mma_gemm_kernel,
                         cudaFuncAttributeMaxDynamicSharedMemorySize, SMEM_TOTAL);

    prep_kernel<<<(M_ * E_ / 4 + 255) / 256, 256>>>(x, W);

    dim3 gg(GV_ / 128, M_ / 256);   // (5, 128)
    mma_gemm_kernel<<<gg, 512, SMEM_TOTAL>>>();

    argmax_gather_kernel<<<(ROWS_ * 32 + 255) / 256, 256>>>(x, u, bias, codebook, out);

    entropy_kernel<<<1, 1024>>>(out, out_size);
}